// round 2
// baseline (speedup 1.0000x reference)
#include <cuda_runtime.h>
#include <math.h>

#define Bsz 32
#define Ssz 512
#define Esz 256
#define HDz 256
#define Hsz 512
#define Lsz 32
#define NG  1024   // 4*HD gate rows per direction

// ------------------- scratch -------------------
__device__ float g_x0[Bsz * Ssz * Esz];                 // embed out
__device__ float g_gx[2 * Bsz * Ssz * NG];              // gate preacts, both dirs
__device__ float g_h0[Bsz * Ssz * Hsz];                 // layer0 out
__device__ float g_h1[Bsz * Ssz * Hsz];                 // layer1 out
__device__ float g_ring[2 * 2 * HDz * Bsz];             // [dir][buf][unit][batch]
__device__ unsigned long long g_bar_cnt = 0ull;
__device__ unsigned long long g_bar_gen = 0ull;

// ------------------- embed -------------------
__global__ void k_embed(const int* __restrict__ x, const float* __restrict__ emb,
                        float* __restrict__ out) {
    int row = blockIdx.x;
    int t = threadIdx.x;               // 64 threads
    int tok = x[row];
    const float4* s = (const float4*)(emb + (size_t)tok * Esz);
    ((float4*)(out + (size_t)row * Esz))[t] = s[t];
}

// ------------------- GEMM: C[M,N] = A[M,K] @ W[N,K]^T + b1 + b2 -------------------
// BM=BN=128, BK=8, 256 threads, 8x8 per thread
__global__ __launch_bounds__(256) void k_gemm(const float* __restrict__ A,
                                              const float* __restrict__ W,
                                              const float* __restrict__ b1,
                                              const float* __restrict__ b2,
                                              float* __restrict__ C,
                                              int K, int N) {
    __shared__ __align__(16) float As[8][132];
    __shared__ __align__(16) float Bs[8][132];
    int m0 = blockIdx.y * 128, n0 = blockIdx.x * 128;
    int tid = threadIdx.x;
    int tx = tid & 15, ty = tid >> 4;
    int lr = tid >> 1;
    int lk = (tid & 1) * 4;
    const float* Ap = A + (size_t)(m0 + lr) * K + lk;
    const float* Wp = W + (size_t)(n0 + lr) * K + lk;

    float acc[8][8];
#pragma unroll
    for (int i = 0; i < 8; i++)
#pragma unroll
        for (int j = 0; j < 8; j++) acc[i][j] = 0.f;

    float4 av = *(const float4*)(Ap);
    float4 bv = *(const float4*)(Wp);

    for (int k0 = 0; k0 < K; k0 += 8) {
        __syncthreads();
        As[lk + 0][lr] = av.x; As[lk + 1][lr] = av.y;
        As[lk + 2][lr] = av.z; As[lk + 3][lr] = av.w;
        Bs[lk + 0][lr] = bv.x; Bs[lk + 1][lr] = bv.y;
        Bs[lk + 2][lr] = bv.z; Bs[lk + 3][lr] = bv.w;
        __syncthreads();
        float4 av_n = av, bv_n = bv;
        if (k0 + 8 < K) {
            av_n = *(const float4*)(Ap + k0 + 8);
            bv_n = *(const float4*)(Wp + k0 + 8);
        }
#pragma unroll
        for (int kk = 0; kk < 8; kk++) {
            float4 a0 = *(const float4*)&As[kk][ty * 4];
            float4 a1 = *(const float4*)&As[kk][64 + ty * 4];
            float4 c0 = *(const float4*)&Bs[kk][tx * 4];
            float4 c1 = *(const float4*)&Bs[kk][64 + tx * 4];
            float a_[8] = {a0.x, a0.y, a0.z, a0.w, a1.x, a1.y, a1.z, a1.w};
            float b_[8] = {c0.x, c0.y, c0.z, c0.w, c1.x, c1.y, c1.z, c1.w};
#pragma unroll
            for (int i = 0; i < 8; i++)
#pragma unroll
                for (int j = 0; j < 8; j++) acc[i][j] += a_[i] * b_[j];
        }
        av = av_n; bv = bv_n;
    }

#pragma unroll
    for (int i = 0; i < 8; i++) {
        int r = m0 + ((i < 4) ? ty * 4 + i : 64 + ty * 4 + i - 4);
#pragma unroll
        for (int j = 0; j < 8; j++) {
            int c = n0 + ((j < 4) ? tx * 4 + j : 64 + tx * 4 + j - 4);
            C[(size_t)r * N + c] = acc[i][j] + b1[c] + b2[c];
        }
    }
}

// ------------------- grid barrier (128 co-resident CTAs) -------------------
__device__ __forceinline__ void grid_bar() {
    __threadfence();
    __syncthreads();
    if (threadIdx.x == 0) {
        unsigned long long tk = atomicAdd(&g_bar_cnt, 1ull);
        unsigned long long target = tk / 128ull + 1ull;
        if ((tk % 128ull) == 127ull) {
            atomicExch(&g_bar_gen, target);
        } else {
            while (atomicAdd(&g_bar_gen, 0ull) < target) __nanosleep(200);
        }
    }
    __syncthreads();
}

__device__ __forceinline__ float sigm(float x) { return 1.f / (1.f + expf(-x)); }

// ------------------- BiLSTM recurrence (one layer, both dirs) -------------------
// grid 128 CTAs x 128 threads. CTA: dir = bid>>6, chunk = bid&63 -> units [4c,4c+4)
__global__ __launch_bounds__(128) void k_recur(const float* __restrict__ gx,
                                               const float* __restrict__ w_hh,
                                               const int* __restrict__ xlen,
                                               float* __restrict__ hout) {
    __shared__ __align__(16) float w_s[256 * 16];   // [k][col], col = u_l*4+gate
    __shared__ __align__(16) float h_s[256 * 32];   // [unit k][batch]
    int dir = blockIdx.x >> 6;
    int chunk = blockIdx.x & 63;
    int u0 = chunk * 4;
    int tid = threadIdx.x;
    int rp = tid >> 4, bp = tid & 15;
    int odd = rp & 1;

    const float* wd = w_hh + (size_t)dir * NG * HDz;
    const float* gxd = gx + (size_t)dir * Bsz * Ssz * NG;
    float* ring = g_ring + dir * 2 * HDz * Bsz;

    for (int idx = tid; idx < 4096; idx += 128) {
        int col = idx >> 8;
        int k = idx & 255;
        int u_l = col >> 2, gate = col & 3;
        w_s[k * 16 + col] = wd[(size_t)(gate * 256 + u0 + u_l) * HDz + k];
    }

    int u = rp >> 1;
    int b = 2 * bp + odd;
    int ug = u0 + u;
    ring[ug * 32 + b] = 0.f;  // zero buf0

    int len_b0 = xlen[2 * bp], len_b1 = xlen[2 * bp + 1];
    int mylen = odd ? len_b1 : len_b0;

    int c0 = 2 * rp, c1 = 2 * rp + 1;
    int grow0 = (c0 & 3) * 256 + u0 + (c0 >> 2);
    int grow1 = (c1 & 3) * 256 + u0 + (c1 >> 2);

    float c_st = 0.f, h_st = 0.f;
    grid_bar();

    const float2* w_s2 = (const float2*)w_s;
    const float2* h_s2 = (const float2*)h_s;

    for (int t = 0; t < 512; t++) {
        const float4* rc = (const float4*)(ring + (t & 1) * HDz * Bsz);
        float4* hs4 = (float4*)h_s;
#pragma unroll
        for (int i = 0; i < 16; i++) hs4[tid + i * 128] = __ldcv(rc + tid + i * 128);

        int s0 = t, s1 = t;
        if (dir) {
            s0 = (t < len_b0) ? (len_b0 - 1 - t) : t;
            s1 = (t < len_b1) ? (len_b1 - 1 - t) : t;
        }
        float g00 = gxd[((size_t)(2 * bp) * Ssz + s0) * NG + grow0];
        float g01 = gxd[((size_t)(2 * bp + 1) * Ssz + s1) * NG + grow0];
        float g10 = gxd[((size_t)(2 * bp) * Ssz + s0) * NG + grow1];
        float g11 = gxd[((size_t)(2 * bp + 1) * Ssz + s1) * NG + grow1];
        __syncthreads();

        float a00 = 0.f, a01 = 0.f, a10 = 0.f, a11 = 0.f;
#pragma unroll 8
        for (int k = 0; k < 256; k++) {
            float2 w2 = w_s2[k * 8 + rp];
            float2 hb = h_s2[k * 16 + bp];
            a00 += w2.x * hb.x; a01 += w2.x * hb.y;
            a10 += w2.y * hb.x; a11 += w2.y * hb.y;
        }
        a00 += g00; a01 += g01; a10 += g10; a11 += g11;

        float sx = odd ? a00 : a01;
        float sy = odd ? a10 : a11;
        float rx = __shfl_xor_sync(0xffffffffu, sx, 16);
        float ry = __shfl_xor_sync(0xffffffffu, sy, 16);
        float gi, gf, gg, go;
        if (!odd) { gi = a00; gf = a10; gg = rx;  go = ry;  }
        else      { gi = rx;  gf = ry;  gg = a01; go = a11; }

        float iv = sigm(gi), fv = sigm(gf), ov = sigm(go), gv = tanhf(gg);
        float cn = fv * c_st + iv * gv;
        float hn = ov * tanhf(cn);
        bool m = t < mylen;
        c_st = m ? cn : c_st;
        h_st = m ? hn : h_st;
        float outv = m ? hn : 0.f;

        ring[((t + 1) & 1) * HDz * Bsz + ug * 32 + b] = h_st;
        int pos, col;
        if (!dir) { pos = t; col = ug; }
        else      { pos = m ? (mylen - 1 - t) : t; col = 256 + ug; }
        hout[((size_t)b * Ssz + pos) * Hsz + col] = outv;

        grid_bar();
    }
}

// ------------------- emissions: out[M,32] = h[M,512] @ dw[32,512]^T + db -------------------
__global__ __launch_bounds__(256) void k_emis(const float* __restrict__ h,
                                              const float* __restrict__ dw,
                                              const float* __restrict__ db,
                                              float* __restrict__ out) {
    __shared__ float wT[128 * 33];
    __shared__ float hs[32 * 128];
    int tid = threadIdx.x;
    int w = tid >> 5, j = tid & 31;
    int row0 = blockIdx.x * 32;
    float acc[4] = {0.f, 0.f, 0.f, 0.f};
    for (int kc = 0; kc < 4; kc++) {
        __syncthreads();
        for (int idx = tid; idx < 4096; idx += 256) {
            int jj = idx >> 7, k = idx & 127;
            wT[k * 33 + jj] = dw[(size_t)jj * 512 + kc * 128 + k];
        }
        for (int idx = tid; idx < 4096; idx += 256) {
            int r = idx >> 7, k = idx & 127;
            hs[r * 128 + k] = h[(size_t)(row0 + r) * 512 + kc * 128 + k];
        }
        __syncthreads();
#pragma unroll 4
        for (int k = 0; k < 128; k++) {
            float wv = wT[k * 33 + j];
#pragma unroll
            for (int i = 0; i < 4; i++) acc[i] += hs[(w * 4 + i) * 128 + k] * wv;
        }
    }
    float bias = db[j];
#pragma unroll
    for (int i = 0; i < 4; i++)
        out[(size_t)(row0 + w * 4 + i) * 32 + j] = acc[i] + bias;
}

// ------------------- Viterbi: 32 blocks x 32 threads -------------------
__global__ void k_viterbi(const float* __restrict__ em, const int* __restrict__ xlen,
                          const float* __restrict__ trans, const float* __restrict__ st,
                          const float* __restrict__ et,
                          float* __restrict__ tags_out, float* __restrict__ scores_out) {
    __shared__ unsigned char bp[512][32];
    int b = blockIdx.x, j = threadIdx.x;
    int len = xlen[b];
    float tc[32];
#pragma unroll
    for (int i = 0; i < 32; i++) tc[i] = trans[i * 32 + j];
    const float* e = em + (size_t)b * Ssz * Lsz;
    float alpha = st[j] + e[j];
    for (int t = 1; t < 512; t++) {
        if (t < len) {
            float best = -1e30f; int arg = 0;
#pragma unroll
            for (int i = 0; i < 32; i++) {
                float ai = __shfl_sync(0xffffffffu, alpha, i);
                float cand = ai + tc[i];
                if (cand > best) { best = cand; arg = i; }
            }
            alpha = best + e[(size_t)t * 32 + j];
            bp[t][j] = (unsigned char)arg;
        } else {
            bp[t][j] = (unsigned char)j;
        }
    }
    __syncwarp();
    float fin = alpha + et[j];
    float bv = fin; int bi = j;
#pragma unroll
    for (int off = 16; off; off >>= 1) {
        float ovv = __shfl_down_sync(0xffffffffu, bv, off);
        int oi = __shfl_down_sync(0xffffffffu, bi, off);
        if (ovv > bv || (ovv == bv && oi < bi)) { bv = ovv; bi = oi; }
    }
    if (j == 0) {
        scores_out[b] = bv;
        int tg = bi;
        for (int t = 511; t >= 1; t--) {
            tags_out[(size_t)b * Ssz + t] = (t < len) ? (float)tg : 0.f;
            tg = bp[t][tg];
        }
        tags_out[(size_t)b * Ssz] = (float)tg;
    }
}

// ------------------- launch -------------------
extern "C" void kernel_launch(void* const* d_in, const int* in_sizes, int n_in,
                              void* d_out, int out_size) {
    const int*   x       = (const int*)d_in[0];
    const int*   xlen    = (const int*)d_in[1];
    const float* emb     = (const float*)d_in[2];
    const float* w_ih_l0 = (const float*)d_in[3];
    const float* w_hh_l0 = (const float*)d_in[4];
    const float* b_ih_l0 = (const float*)d_in[5];
    const float* b_hh_l0 = (const float*)d_in[6];
    const float* w_ih_l1 = (const float*)d_in[7];
    const float* w_hh_l1 = (const float*)d_in[8];
    const float* b_ih_l1 = (const float*)d_in[9];
    const float* b_hh_l1 = (const float*)d_in[10];
    const float* dw      = (const float*)d_in[11];
    const float* db      = (const float*)d_in[12];
    const float* trans   = (const float*)d_in[13];
    const float* strn    = (const float*)d_in[14];
    const float* etrn    = (const float*)d_in[15];
    float* out = (float*)d_out;

    float *x0, *gx, *h0, *h1;
    cudaGetSymbolAddress((void**)&x0, g_x0);
    cudaGetSymbolAddress((void**)&gx, g_gx);
    cudaGetSymbolAddress((void**)&h0, g_h0);
    cudaGetSymbolAddress((void**)&h1, g_h1);

    const size_t GXD = (size_t)Bsz * Ssz * NG;

    k_embed<<<Bsz * Ssz, 64>>>(x, emb, x0);

    // layer 0: K=256
    k_gemm<<<dim3(8, 128), 256>>>(x0, w_ih_l0,              b_ih_l0,        b_hh_l0,        gx,       256, NG);
    k_gemm<<<dim3(8, 128), 256>>>(x0, w_ih_l0 + NG * 256,   b_ih_l0 + NG,   b_hh_l0 + NG,   gx + GXD, 256, NG);
    k_recur<<<128, 128>>>(gx, w_hh_l0, xlen, h0);

    // layer 1: K=512
    k_gemm<<<dim3(8, 128), 256>>>(h0, w_ih_l1,              b_ih_l1,        b_hh_l1,        gx,       512, NG);
    k_gemm<<<dim3(8, 128), 256>>>(h0, w_ih_l1 + NG * 512,   b_ih_l1 + NG,   b_hh_l1 + NG,   gx + GXD, 512, NG);
    k_recur<<<128, 128>>>(gx, w_hh_l1, xlen, h1);

    k_emis<<<512, 256>>>(h1, dw, db, out);

    float* tags   = out + (size_t)Bsz * Ssz * Lsz;
    float* scores = tags + (size_t)Bsz * Ssz;
    k_viterbi<<<Bsz, 32>>>(out, xlen, trans, strn, etrn, tags, scores);
}